// round 1
// baseline (speedup 1.0000x reference)
#include <cuda_runtime.h>

// Problem constants
#define HH    224
#define WW    224
#define CCH   256
#define FF    256
#define OBS   14     // output block size
#define NTILES 1024  // 4 * 16 * 16
#define CCHUNK 8     // C channels per smem chunk

__device__ int g_active[NTILES];

// ---------------------------------------------------------------------------
// Stage 1: per-tile active mask.  pooled = mean over 16x16 padded mask block;
// active = pooled > 0.5  <=>  sum > 128.  Double accumulation so our sum is
// essentially exact (flipping a tile vs the reference costs ~3e-2 rel err).
// ---------------------------------------------------------------------------
__global__ void active_kernel(const float* __restrict__ mask) {
    int tile = blockIdx.x;
    int n  = tile >> 8;
    int bi = (tile >> 4) & 15;
    int bj = tile & 15;
    int tid = threadIdx.x;           // 256 threads
    int j = tid >> 4;                // 0..15 block row
    int i = tid & 15;                // 0..15 block col
    int r = bi * OBS + j - 1;        // original-image row (pad=1)
    int c = bj * OBS + i - 1;
    float v = 0.0f;
    if (r >= 0 && r < HH && c >= 0 && c < WW)
        v = mask[(n * HH + r) * WW + c];

    __shared__ double s[256];
    s[tid] = (double)v;
    __syncthreads();
    for (int off = 128; off > 0; off >>= 1) {
        if (tid < off) s[tid] += s[tid + off];
        __syncthreads();
    }
    if (tid == 0) g_active[tile] = (s[0] > 128.0) ? 1 : 0;
}

// ---------------------------------------------------------------------------
// Stage 2: per-tile 3x3 conv + bias + relu, skipped (zero-filled) when the
// tile is inactive.  Block = 224 threads = 14 output rows x 16 f-groups.
// Each thread accumulates 14 px x 4 f in registers.  C is chunked by 8
// through shared memory; input rows padded to stride 17 (odd) so the 14
// row-threads hit distinct banks.
// ---------------------------------------------------------------------------
__global__ void __launch_bounds__(224)
conv_kernel(const float* __restrict__ in,
            const float* __restrict__ wt,     // (3,3,C,F)
            const float* __restrict__ bias,   // (F)
            float* __restrict__ out)
{
    int tile = blockIdx.x;
    int fc   = blockIdx.y;           // 0..3  (64 F channels each)
    int n  = tile >> 8;
    int bi = (tile >> 4) & 15;
    int bj = tile & 15;

    int tid = threadIdx.x;
    int row = tid >> 4;              // 0..13 output row within tile
    int fg  = tid & 15;              // 0..15 f-group (4 consecutive f)
    int fbase = fc * 64 + fg * 4;

    int oy = bi * OBS + row;
    float* outrow = out + ((size_t)(n * HH + oy) * WW + bj * OBS) * FF + fbase;

    if (!g_active[tile]) {
        float4 z = make_float4(0.f, 0.f, 0.f, 0.f);
        #pragma unroll
        for (int px = 0; px < OBS; px++)
            *reinterpret_cast<float4*>(outrow + px * FF) = z;
        return;
    }

    __shared__ float s_in[CCHUNK][16 * 17];   // [c][r*17 + col]
    __shared__ float s_w[9][CCHUNK][64];      // [ky*3+kx][c][f]

    float acc[OBS][4];
    #pragma unroll
    for (int p = 0; p < OBS; p++) {
        acc[p][0] = 0.f; acc[p][1] = 0.f; acc[p][2] = 0.f; acc[p][3] = 0.f;
    }

    const int r0 = bi * OBS - 1;
    const int c0 = bj * OBS - 1;

    for (int cc = 0; cc < CCH; cc += CCHUNK) {
        __syncthreads();
        // --- load input chunk: 16x16 positions x CCHUNK channels ---
        for (int idx = tid; idx < 256 * (CCHUNK / 4); idx += 224) {
            int pos = idx / (CCHUNK / 4);
            int h4  = idx % (CCHUNK / 4);
            int rr  = pos >> 4;
            int cl  = pos & 15;
            int r = r0 + rr;
            int c = c0 + cl;
            float4 v = make_float4(0.f, 0.f, 0.f, 0.f);
            if (r >= 0 && r < HH && c >= 0 && c < WW)
                v = *reinterpret_cast<const float4*>(
                        in + ((size_t)(n * HH + r) * WW + c) * CCH + cc + h4 * 4);
            s_in[h4 * 4 + 0][rr * 17 + cl] = v.x;
            s_in[h4 * 4 + 1][rr * 17 + cl] = v.y;
            s_in[h4 * 4 + 2][rr * 17 + cl] = v.z;
            s_in[h4 * 4 + 3][rr * 17 + cl] = v.w;
        }
        // --- load weight chunk: 9 x CCHUNK x 64 floats ---
        for (int idx = tid; idx < 9 * CCHUNK * 16; idx += 224) {
            int f4   = idx & 15;
            int rest = idx >> 4;            // kk*CCHUNK + c
            int kk = rest / CCHUNK;
            int c  = rest % CCHUNK;
            float4 v = *reinterpret_cast<const float4*>(
                    wt + ((size_t)kk * CCH + cc + c) * FF + fc * 64 + f4 * 4);
            *reinterpret_cast<float4*>(&s_w[kk][c][f4 * 4]) = v;
        }
        __syncthreads();

        // --- compute ---
        #pragma unroll
        for (int c = 0; c < CCHUNK; c++) {
            #pragma unroll
            for (int ky = 0; ky < 3; ky++) {
                float iv[16];
                #pragma unroll
                for (int t = 0; t < 16; t++)
                    iv[t] = s_in[c][(row + ky) * 17 + t];
                #pragma unroll
                for (int kx = 0; kx < 3; kx++) {
                    float4 w = *reinterpret_cast<float4*>(&s_w[ky * 3 + kx][c][fg * 4]);
                    #pragma unroll
                    for (int px = 0; px < OBS; px++) {
                        float x = iv[px + kx];
                        acc[px][0] += x * w.x;
                        acc[px][1] += x * w.y;
                        acc[px][2] += x * w.z;
                        acc[px][3] += x * w.w;
                    }
                }
            }
        }
    }

    float4 b = *reinterpret_cast<const float4*>(bias + fbase);
    #pragma unroll
    for (int px = 0; px < OBS; px++) {
        float4 o;
        o.x = fmaxf(acc[px][0] + b.x, 0.f);
        o.y = fmaxf(acc[px][1] + b.y, 0.f);
        o.z = fmaxf(acc[px][2] + b.z, 0.f);
        o.w = fmaxf(acc[px][3] + b.w, 0.f);
        *reinterpret_cast<float4*>(outrow + px * FF) = o;
    }
}

extern "C" void kernel_launch(void* const* d_in, const int* in_sizes, int n_in,
                              void* d_out, int out_size) {
    const float* inputs = (const float*)d_in[0];   // (4,224,224,256)
    const float* mask   = (const float*)d_in[1];   // (4,224,224,1)
    const float* kernel = (const float*)d_in[2];   // (3,3,256,256)
    const float* bias   = (const float*)d_in[3];   // (256)
    float* out = (float*)d_out;                    // (4,224,224,256)

    active_kernel<<<NTILES, 256>>>(mask);
    dim3 grid(NTILES, 4);
    conv_kernel<<<grid, 224>>>(inputs, kernel, bias, out);
}

// round 4
// speedup vs baseline: 2.0655x; 2.0655x over previous
#include <cuda_runtime.h>
#include <cuda_fp16.h>
#include <cstdint>

#define NTILES 1024

__device__ int g_active[NTILES];
__device__ __align__(16) __half g_wt_h[9 * 256 * 256];   // [pos][f][c] fp16 hi
__device__ __align__(16) __half g_wt_l[9 * 256 * 256];   // [pos][f][c] fp16 lo

// ---------------- helpers ----------------
__device__ __forceinline__ uint32_t smem_to_u32(const void* p) {
    uint32_t a;
    asm("{ .reg .u64 t; cvta.to.shared.u64 t, %1; cvt.u32.u64 %0, t; }" : "=r"(a) : "l"(p));
    return a;
}
__device__ __forceinline__ void ldsm4(uint32_t* r, uint32_t addr) {
    asm volatile("ldmatrix.sync.aligned.m8n8.x4.shared.b16 {%0,%1,%2,%3}, [%4];"
                 : "=r"(r[0]), "=r"(r[1]), "=r"(r[2]), "=r"(r[3]) : "r"(addr));
}
__device__ __forceinline__ void mma16816(float* d, const uint32_t* a, const uint32_t* b) {
    asm volatile(
        "mma.sync.aligned.m16n8k16.row.col.f32.f16.f16.f32 "
        "{%0,%1,%2,%3}, {%4,%5,%6,%7}, {%8,%9}, {%0,%1,%2,%3};"
        : "+f"(d[0]), "+f"(d[1]), "+f"(d[2]), "+f"(d[3])
        : "r"(a[0]), "r"(a[1]), "r"(a[2]), "r"(a[3]), "r"(b[0]), "r"(b[1]));
}

// ---------------- Stage 0: weight transpose + fp16 hi/lo split ----------------
// wt (3,3,256,256) fp32 [pos][c][f]  ->  [pos][f][c] fp16 hi & lo
__global__ void __launch_bounds__(256) wt_prep(const float* __restrict__ wt) {
    int pos = blockIdx.x >> 8;    // 0..8
    int f   = blockIdx.x & 255;
    int c   = threadIdx.x;
    float x = wt[((size_t)((pos << 8) | c)) * 256 + f];
    __half h = __float2half_rn(x);
    float r = x - __half2float(h);
    __half lo = __float2half_rn(r);
    size_t di = ((size_t)((pos << 8) | f)) * 256 + c;
    g_wt_h[di] = h;
    g_wt_l[di] = lo;
}

// ---------------- Stage 1: active mask (exact) ----------------
__global__ void __launch_bounds__(256) active_kernel(const float* __restrict__ mask) {
    int tile = blockIdx.x;
    int n = tile >> 8, bi = (tile >> 4) & 15, bj = tile & 15;
    int tid = threadIdx.x;
    int j = tid >> 4, i = tid & 15;
    int r = bi * 14 + j - 1;
    int c = bj * 14 + i - 1;
    float v = 0.0f;
    if (r >= 0 && r < 224 && c >= 0 && c < 224) v = mask[(n * 224 + r) * 224 + c];
    __shared__ double s[256];
    s[tid] = (double)v;
    __syncthreads();
    for (int off = 128; off > 0; off >>= 1) {
        if (tid < off) s[tid] += s[tid + off];
        __syncthreads();
    }
    if (tid == 0) g_active[tile] = (s[0] > 128.0) ? 1 : 0;
}

// ---------------- Stage 2: implicit-GEMM conv via mma.sync ----------------
// smem: A rows = 258 patch rows (16*16 px + 2 pad), 48B padded rows of 16 fp16 ch
//       W rows = 9 pos * 64 f, 48B padded rows of 16 fp16 ch
#define OFF_AH 0u
#define OFF_AL 12384u
#define OFF_WH 24768u
#define OFF_WL 52416u
#define SMEM_DYN 80064

__global__ void __launch_bounds__(256, 2)
conv_kernel(const float* __restrict__ in,
            const float* __restrict__ bias,
            float* __restrict__ out)
{
    const int tile = blockIdx.x;
    const int fq   = blockIdx.y;         // 0..3 -> 64 F channels
    const int n = tile >> 8, bi = (tile >> 4) & 15, bj = tile & 15;
    const int tid = threadIdx.x;

    // ---- inactive: zero-fill this CTA's slice and exit ----
    if (!g_active[tile]) {
        float4 z = make_float4(0.f, 0.f, 0.f, 0.f);
        for (int i = tid; i < 196 * 16; i += 256) {
            int px = i >> 4, q = i & 15;
            int oy = px / 14, ox = px - oy * 14;
            size_t o = (((size_t)(n * 224 + bi * 14 + oy)) * 224 + bj * 14 + ox) * 256
                       + fq * 64 + q * 4;
            *reinterpret_cast<float4*>(out + o) = z;
        }
        return;
    }

    extern __shared__ char sm[];
    const uint32_t sb = smem_to_u32(sm);

    const int l   = tid & 31;
    const int wid = tid >> 5;
    const int wm  = wid >> 2;            // 0..1 : M half (112 rows)
    const int wn  = wid & 3;             // 0..3 : 16-F slice within 64

    // ldmatrix lane offsets (A: rows=m, 16 fp16/row; W: rows=f)
    const uint32_t a_lane = (uint32_t)((l & 15) * 48 + ((l >> 4) << 4));
    const uint32_t w_lane = (uint32_t)((wn * 16 + ((l >> 4) & 1) * 8 + (l & 7)) * 48
                                       + ((l >> 3) & 1) * 16);
    const uint32_t abase48 = (uint32_t)(wm * 112 * 48);

    const int r0 = bi * 14 - 1;
    const int c0 = bj * 14 - 1;

    // zero the 2 pad rows (96 bytes each buffer; garbage lanes read them)
    if (tid < 24) {
        *reinterpret_cast<uint32_t*>(sm + OFF_AH + 256 * 48 + tid * 4) = 0;
        *reinterpret_cast<uint32_t*>(sm + OFF_AL + 256 * 48 + tid * 4) = 0;
    }

    float acc[7][8];
    #pragma unroll
    for (int t = 0; t < 7; t++)
        #pragma unroll
        for (int j = 0; j < 8; j++) acc[t][j] = 0.f;

    for (int cc = 0; cc < 16; cc++) {
        __syncthreads();
        // ---- load A: 256 px x 16 ch fp32 -> fp16 hi/lo ----
        #pragma unroll
        for (int i = tid; i < 1024; i += 256) {
            int px = i >> 2, q = i & 3;
            int pr = px >> 4, pc = px & 15;
            int r = r0 + pr, c = c0 + pc;
            float4 v = make_float4(0.f, 0.f, 0.f, 0.f);
            if ((unsigned)r < 224u && (unsigned)c < 224u)
                v = *reinterpret_cast<const float4*>(
                        in + (((size_t)(n * 224 + r)) * 224 + c) * 256 + cc * 16 + q * 4);
            __half hx = __float2half_rn(v.x), hy = __float2half_rn(v.y);
            __half hz = __float2half_rn(v.z), hw = __float2half_rn(v.w);
            __half lx = __float2half_rn(v.x - __half2float(hx));
            __half ly = __float2half_rn(v.y - __half2float(hy));
            __half lz = __float2half_rn(v.z - __half2float(hz));
            __half lw = __float2half_rn(v.w - __half2float(hw));
            uint2 hp, lp;
            hp.x = (uint32_t)__half_as_ushort(hx) | ((uint32_t)__half_as_ushort(hy) << 16);
            hp.y = (uint32_t)__half_as_ushort(hz) | ((uint32_t)__half_as_ushort(hw) << 16);
            lp.x = (uint32_t)__half_as_ushort(lx) | ((uint32_t)__half_as_ushort(ly) << 16);
            lp.y = (uint32_t)__half_as_ushort(lz) | ((uint32_t)__half_as_ushort(lw) << 16);
            *reinterpret_cast<uint2*>(sm + OFF_AH + px * 48 + q * 8) = hp;
            *reinterpret_cast<uint2*>(sm + OFF_AL + px * 48 + q * 8) = lp;
        }
        // ---- load W: 9 pos x 64 f x 16 ch (pre-split fp16) ----
        #pragma unroll
        for (int i = tid; i < 1152; i += 256) {
            int row = i >> 1, seg = i & 1;
            int pos = row >> 6, f = row & 63;
            size_t gi = ((size_t)((pos << 8) | (fq * 64 + f))) * 256 + cc * 16 + seg * 8;
            *reinterpret_cast<uint4*>(sm + OFF_WH + row * 48 + seg * 16) =
                *reinterpret_cast<const uint4*>(g_wt_h + gi);
            *reinterpret_cast<uint4*>(sm + OFF_WL + row * 48 + seg * 16) =
                *reinterpret_cast<const uint4*>(g_wt_l + gi);
        }
        __syncthreads();

        #pragma unroll 1
        for (int pos = 0; pos < 9; pos++) {
            const int ky = pos / 3, kx = pos - ky * 3;
            const uint32_t woff = w_lane + (uint32_t)pos * 3072u;
            uint32_t wh[4], wl[4];
            ldsm4(wh, sb + OFF_WH + woff);
            ldsm4(wl, sb + OFF_WL + woff);

            const uint32_t ash = a_lane + abase48 + (uint32_t)(ky * 16 + kx) * 48u;
            uint32_t a[7][4];
            #pragma unroll
            for (int t = 0; t < 7; t++)
                ldsm4(a[t], sb + OFF_AH + ash + (uint32_t)t * 768u);
            #pragma unroll
            for (int t = 0; t < 7; t++) {
                mma16816(acc[t],     a[t], wh);
                mma16816(acc[t] + 4, a[t], wh + 2);
            }
            #pragma unroll
            for (int t = 0; t < 7; t++) {
                mma16816(acc[t],     a[t], wl);
                mma16816(acc[t] + 4, a[t], wl + 2);
            }
            #pragma unroll
            for (int t = 0; t < 7; t++)
                ldsm4(a[t], sb + OFF_AL + ash + (uint32_t)t * 768u);
            #pragma unroll
            for (int t = 0; t < 7; t++) {
                mma16816(acc[t],     a[t], wh);
                mma16816(acc[t] + 4, a[t], wh + 2);
            }
        }
    }

    // ---- epilogue: bias + relu + store ----
    const int f0 = fq * 64 + wn * 16 + (l & 3) * 2;
    const float b00 = bias[f0],     b01 = bias[f0 + 1];
    const float b10 = bias[f0 + 8], b11 = bias[f0 + 9];

    #pragma unroll
    for (int t = 0; t < 7; t++) {
        int m_lo = wm * 112 + t * 16 + (l >> 2);
        #pragma unroll
        for (int h = 0; h < 2; h++) {
            int m = m_lo + h * 8;
            int oy = m >> 4, ox = m & 15;
            if (ox < 14) {
                float* p = out + (((size_t)(n * 224 + bi * 14 + oy)) * 224
                                  + bj * 14 + ox) * 256 + f0;
                float2 v0, v1;
                v0.x = fmaxf(acc[t][h * 2 + 0] + b00, 0.f);
                v0.y = fmaxf(acc[t][h * 2 + 1] + b01, 0.f);
                v1.x = fmaxf(acc[t][h * 2 + 4] + b10, 0.f);
                v1.y = fmaxf(acc[t][h * 2 + 5] + b11, 0.f);
                *reinterpret_cast<float2*>(p) = v0;
                *reinterpret_cast<float2*>(p + 8) = v1;
            }
        }
    }
}

extern "C" void kernel_launch(void* const* d_in, const int* in_sizes, int n_in,
                              void* d_out, int out_size) {
    const float* inputs = (const float*)d_in[0];   // (4,224,224,256)
    const float* mask   = (const float*)d_in[1];   // (4,224,224,1)
    const float* kernel = (const float*)d_in[2];   // (3,3,256,256)
    const float* bias   = (const float*)d_in[3];   // (256)
    float* out = (float*)d_out;                    // (4,224,224,256)

    cudaFuncSetAttribute(conv_kernel, cudaFuncAttributeMaxDynamicSharedMemorySize, SMEM_DYN);

    active_kernel<<<NTILES, 256>>>(mask);
    wt_prep<<<9 * 256, 256>>>(kernel);
    dim3 grid(NTILES, 4);
    conv_kernel<<<grid, 256, SMEM_DYN>>>(inputs, bias, out);
}

// round 5
// speedup vs baseline: 3.1340x; 1.5173x over previous
#include <cuda_runtime.h>
#include <cuda_fp16.h>
#include <cstdint>

#define NTILES 1024

__device__ int g_active[NTILES];
__device__ __align__(16) __half g_wt_h[9 * 256 * 256];    // [pos][f][c] fp16 hi
__device__ __align__(16) __half g_wt_l[9 * 256 * 256];    // [pos][f][c] fp16 lo
__device__ __align__(16) __half g_in_h[4 * 224 * 224 * 256];  // input fp16 hi
__device__ __align__(16) __half g_in_l[4 * 224 * 224 * 256];  // input fp16 lo

// ---------------- helpers ----------------
__device__ __forceinline__ uint32_t smem_to_u32(const void* p) {
    uint32_t a;
    asm("{ .reg .u64 t; cvta.to.shared.u64 t, %1; cvt.u32.u64 %0, t; }" : "=r"(a) : "l"(p));
    return a;
}
__device__ __forceinline__ void ldsm4(uint32_t* r, uint32_t addr) {
    asm volatile("ldmatrix.sync.aligned.m8n8.x4.shared.b16 {%0,%1,%2,%3}, [%4];"
                 : "=r"(r[0]), "=r"(r[1]), "=r"(r[2]), "=r"(r[3]) : "r"(addr));
}
__device__ __forceinline__ void mma16816(float* d, const uint32_t* a, const uint32_t* b) {
    asm volatile(
        "mma.sync.aligned.m16n8k16.row.col.f32.f16.f16.f32 "
        "{%0,%1,%2,%3}, {%4,%5,%6,%7}, {%8,%9}, {%0,%1,%2,%3};"
        : "+f"(d[0]), "+f"(d[1]), "+f"(d[2]), "+f"(d[3])
        : "r"(a[0]), "r"(a[1]), "r"(a[2]), "r"(a[3]), "r"(b[0]), "r"(b[1]));
}
__device__ __forceinline__ void cpasync16(uint32_t dst, const void* src, int sz) {
    asm volatile("cp.async.cg.shared.global [%0], [%1], 16, %2;\n"
                 :: "r"(dst), "l"(src), "r"(sz) : "memory");
}
__device__ __forceinline__ void cpasync16(uint32_t dst, const void* src) {
    asm volatile("cp.async.cg.shared.global [%0], [%1], 16;\n"
                 :: "r"(dst), "l"(src) : "memory");
}
__device__ __forceinline__ void hsplit(float x, unsigned short& h, unsigned short& l) {
    __half hh = __float2half_rn(x);
    __half ll = __float2half_rn(x - __half2float(hh));
    h = __half_as_ushort(hh);
    l = __half_as_ushort(ll);
}

// ---------------- Stage 0 (fused prep): active mask + weight split + input split ----
__global__ void __launch_bounds__(256)
prep_kernel(const float* __restrict__ in,
            const float* __restrict__ mask,
            const float* __restrict__ wt)
{
    const int b = blockIdx.x;
    const int tid = threadIdx.x;
    if (b < 1024) {
        // ---- active mask (exact, double) ----
        int n = b >> 8, bi = (b >> 4) & 15, bj = b & 15;
        int j = tid >> 4, i = tid & 15;
        int r = bi * 14 + j - 1;
        int c = bj * 14 + i - 1;
        float v = 0.0f;
        if (r >= 0 && r < 224 && c >= 0 && c < 224) v = mask[(n * 224 + r) * 224 + c];
        __shared__ double s[256];
        s[tid] = (double)v;
        __syncthreads();
        for (int off = 128; off > 0; off >>= 1) {
            if (tid < off) s[tid] += s[tid + off];
            __syncthreads();
        }
        if (tid == 0) g_active[b] = (s[0] > 128.0) ? 1 : 0;
    } else if (b < 1024 + 2304) {
        // ---- weight transpose + split: [pos][c][f] -> [pos][f][c] hi/lo ----
        int bb = b - 1024;
        int pos = bb >> 8, f = bb & 255, c = tid;
        float x = wt[((size_t)((pos << 8) | c)) * 256 + f];
        unsigned short h, l;
        hsplit(x, h, l);
        size_t di = ((size_t)((pos << 8) | f)) * 256 + c;
        g_wt_h[di] = __ushort_as_half(h);
        g_wt_l[di] = __ushort_as_half(l);
    } else {
        // ---- input split: fp32 -> fp16 hi/lo, vectorized ----
        size_t idx = (size_t)(b - 3328) * 256 + tid;
        const float4* in4 = reinterpret_cast<const float4*>(in);
        const size_t total4 = 12845056ull;             // 4*224*224*256/4
        const size_t stride = 6144ull * 256ull;
        for (size_t i = idx; i < total4; i += stride) {
            float4 v = in4[i];
            unsigned short h0, h1, h2, h3, l0, l1, l2, l3;
            hsplit(v.x, h0, l0); hsplit(v.y, h1, l1);
            hsplit(v.z, h2, l2); hsplit(v.w, h3, l3);
            uint2 hp, lp;
            hp.x = (uint32_t)h0 | ((uint32_t)h1 << 16);
            hp.y = (uint32_t)h2 | ((uint32_t)h3 << 16);
            lp.x = (uint32_t)l0 | ((uint32_t)l1 << 16);
            lp.y = (uint32_t)l2 | ((uint32_t)l3 << 16);
            *reinterpret_cast<uint2*>(g_in_h + 4 * i) = hp;
            *reinterpret_cast<uint2*>(g_in_l + 4 * i) = lp;
        }
    }
}

// ---------------- Stage 1: pipelined implicit-GEMM conv ----------------
// smem per stage: A = 258 rows x 32B (hi) + same (lo) = 16512 B
//                 W = 576 rows x 32B (hi) + same (lo) = 36864 B
// XOR swizzle: byte(row, half) = row*32 + ((half ^ ((row>>2)&1)) << 4)
#define OFF_A   0u
#define A_STAGE 16512u
#define A_LO    8256u
#define OFF_W   33024u
#define W_STAGE 36864u
#define W_LO    18432u
#define SMEM_DYN 106752

// issue one cc-chunk's cp.async loads (13 x 16B per thread)
__device__ __forceinline__ void issue_stage(uint32_t aBase, uint32_t wBase,
                                            int tid, int n, int r0, int c0,
                                            int fq, int cc)
{
    // A: 1024 ops (256 px x 2 halves x hi/lo)
    #pragma unroll
    for (int k = 0; k < 4; k++) {
        int i = tid + (k << 8);
        int arr  = i >> 9;
        int px   = (i & 511) >> 1;
        int half = i & 1;
        int r = r0 + (px >> 4), c = c0 + (px & 15);
        bool ok = ((unsigned)r < 224u) && ((unsigned)c < 224u);
        int rr = ok ? r : 0, cl = ok ? c : 0;
        const __half* gsrc = arr ? g_in_l : g_in_h;
        const void* src = gsrc + ((((size_t)(n * 224 + rr)) * 224 + cl) * 256
                                  + cc * 16 + half * 8);
        uint32_t dst = aBase + (uint32_t)arr * A_LO + (uint32_t)px * 32u
                     + (uint32_t)((half ^ ((px >> 2) & 1)) << 4);
        cpasync16(dst, src, ok ? 16 : 0);
    }
    // W: 2304 ops (576 rows x 2 halves x hi/lo)
    #pragma unroll
    for (int k = 0; k < 9; k++) {
        int i = tid + (k << 8);
        int arr = (i >= 1152) ? 1 : 0;
        int j = i - arr * 1152;
        int row = j >> 1, half = j & 1;
        int pos = row >> 6, fl = row & 63;
        const __half* gsrc = arr ? g_wt_l : g_wt_h;
        const void* src = gsrc + (((size_t)((pos << 8) | (fq * 64 + fl))) << 8)
                        + cc * 16 + half * 8;
        uint32_t dst = wBase + (uint32_t)arr * W_LO + (uint32_t)row * 32u
                     + (uint32_t)((half ^ ((row >> 2) & 1)) << 4);
        cpasync16(dst, src);
    }
}

__global__ void __launch_bounds__(256, 2)
conv_kernel(const float* __restrict__ bias, float* __restrict__ out)
{
    const int tile = blockIdx.x;
    const int fq   = blockIdx.y;
    const int n = tile >> 8, bi = (tile >> 4) & 15, bj = tile & 15;
    const int tid = threadIdx.x;

    if (!g_active[tile]) {
        float4 z = make_float4(0.f, 0.f, 0.f, 0.f);
        for (int i = tid; i < 196 * 16; i += 256) {
            int px = i >> 4, q = i & 15;
            int oy = px / 14, ox = px - oy * 14;
            size_t o = (((size_t)(n * 224 + bi * 14 + oy)) * 224 + bj * 14 + ox) * 256
                       + fq * 64 + q * 4;
            *reinterpret_cast<float4*>(out + o) = z;
        }
        return;
    }

    extern __shared__ char sm[];
    const uint32_t sb = smem_to_u32(sm);

    const int l   = tid & 31;
    const int wid = tid >> 5;
    const int wm  = wid >> 2;            // 0..1
    const int wn  = wid & 3;             // 0..3

    const int ra0   = wm * 112 + (l & 15);
    const int ahalf = l >> 4;
    const int rw0   = wn * 16 + ((l >> 4) & 1) * 8 + (l & 7);
    const uint32_t woff = (uint32_t)rw0 * 32u
        + (uint32_t)(((((l >> 3) & 1)) ^ ((rw0 >> 2) & 1)) << 4);

    const int r0 = bi * 14 - 1;
    const int c0 = bj * 14 - 1;

    // zero the pad rows (rows 256-257) in all 4 A regions
    if (tid < 64) {
        int s = (tid >> 5) & 1, arr = (tid >> 4) & 1;
        *reinterpret_cast<uint32_t*>(sm + OFF_A + s * A_STAGE + arr * A_LO
                                     + 8192 + (tid & 15) * 4) = 0;
    }

    const uint32_t aS[2] = { sb + OFF_A, sb + OFF_A + A_STAGE };
    const uint32_t wS[2] = { sb + OFF_W, sb + OFF_W + W_STAGE };

    float acc[7][8];
    #pragma unroll
    for (int t = 0; t < 7; t++)
        #pragma unroll
        for (int j = 0; j < 8; j++) acc[t][j] = 0.f;

    // prologue: stage 0
    issue_stage(aS[0], wS[0], tid, n, r0, c0, fq, 0);
    asm volatile("cp.async.commit_group;\n" ::: "memory");

    for (int cc = 0; cc < 16; cc++) {
        const int p = cc & 1;
        if (cc < 15) {
            issue_stage(aS[p ^ 1], wS[p ^ 1], tid, n, r0, c0, fq, cc + 1);
            asm volatile("cp.async.commit_group;\n" ::: "memory");
            asm volatile("cp.async.wait_group 1;\n" ::: "memory");
        } else {
            asm volatile("cp.async.wait_group 0;\n" ::: "memory");
        }
        __syncthreads();

        const uint32_t aB = aS[p];
        const uint32_t wB = wS[p];
        #pragma unroll 1
        for (int pos = 0; pos < 9; pos++) {
            const int ky = pos / 3, kx = pos - ky * 3;
            const int ra = ra0 + ky * 16 + kx;
            const uint32_t aaddr = aB + (uint32_t)ra * 32u
                + (uint32_t)((ahalf ^ ((ra >> 2) & 1)) << 4);
            const uint32_t waddr = wB + (uint32_t)pos * 2048u + woff;

            uint32_t wh[4], wl[4];
            ldsm4(wh, waddr);
            ldsm4(wl, waddr + W_LO);

            uint32_t a[7][4];
            #pragma unroll
            for (int t = 0; t < 7; t++)
                ldsm4(a[t], aaddr + (uint32_t)t * 512u);
            #pragma unroll
            for (int t = 0; t < 7; t++) {
                mma16816(acc[t],     a[t], wh);
                mma16816(acc[t] + 4, a[t], wh + 2);
            }
            #pragma unroll
            for (int t = 0; t < 7; t++) {
                mma16816(acc[t],     a[t], wl);
                mma16816(acc[t] + 4, a[t], wl + 2);
            }
            #pragma unroll
            for (int t = 0; t < 7; t++)
                ldsm4(a[t], aaddr + A_LO + (uint32_t)t * 512u);
            #pragma unroll
            for (int t = 0; t < 7; t++) {
                mma16816(acc[t],     a[t], wh);
                mma16816(acc[t] + 4, a[t], wh + 2);
            }
        }
        __syncthreads();
    }

    // ---- epilogue: bias + relu + store ----
    const int f0 = fq * 64 + wn * 16 + (l & 3) * 2;
    const float b00 = bias[f0],     b01 = bias[f0 + 1];
    const float b10 = bias[f0 + 8], b11 = bias[f0 + 9];

    #pragma unroll
    for (int t = 0; t < 7; t++) {
        int m_lo = wm * 112 + t * 16 + (l >> 2);
        #pragma unroll
        for (int h = 0; h < 2; h++) {
            int m = m_lo + h * 8;
            int oy = m >> 4, ox = m & 15;
            if (ox < 14) {
                float* p = out + (((size_t)(n * 224 + bi * 14 + oy)) * 224
                                  + bj * 14 + ox) * 256 + f0;
                float2 v0, v1;
                v0.x = fmaxf(acc[t][h * 2 + 0] + b00, 0.f);
                v0.y = fmaxf(acc[t][h * 2 + 1] + b01, 0.f);
                v1.x = fmaxf(acc[t][h * 2 + 4] + b10, 0.f);
                v1.y = fmaxf(acc[t][h * 2 + 5] + b11, 0.f);
                *reinterpret_cast<float2*>(p) = v0;
                *reinterpret_cast<float2*>(p + 8) = v1;
            }
        }
    }
}

extern "C" void kernel_launch(void* const* d_in, const int* in_sizes, int n_in,
                              void* d_out, int out_size) {
    const float* inputs = (const float*)d_in[0];   // (4,224,224,256)
    const float* mask   = (const float*)d_in[1];   // (4,224,224,1)
    const float* kernel = (const float*)d_in[2];   // (3,3,256,256)
    const float* bias   = (const float*)d_in[3];   // (256)
    float* out = (float*)d_out;                    // (4,224,224,256)

    cudaFuncSetAttribute(conv_kernel, cudaFuncAttributeMaxDynamicSharedMemorySize, SMEM_DYN);

    prep_kernel<<<9472, 256>>>(inputs, mask, kernel);
    dim3 grid(NTILES, 4);
    conv_kernel<<<grid, 256, SMEM_DYN>>>(bias, out);
}

// round 6
// speedup vs baseline: 3.1515x; 1.0056x over previous
#include <cuda_runtime.h>
#include <cuda_fp16.h>
#include <cstdint>

#define NTILES 1024

__device__ int g_active[NTILES];
__device__ __align__(16) __half g_wt_h[9 * 256 * 256];    // [pos][f][c] fp16 hi
__device__ __align__(16) __half g_wt_l[9 * 256 * 256];    // [pos][f][c] fp16 lo
__device__ __align__(16) __half g_in_h[4 * 224 * 224 * 256];
__device__ __align__(16) __half g_in_l[4 * 224 * 224 * 256];

// ---------------- helpers ----------------
__device__ __forceinline__ uint32_t smem_to_u32(const void* p) {
    uint32_t a;
    asm("{ .reg .u64 t; cvta.to.shared.u64 t, %1; cvt.u32.u64 %0, t; }" : "=r"(a) : "l"(p));
    return a;
}
__device__ __forceinline__ void ldsm4(uint32_t* r, uint32_t addr) {
    asm volatile("ldmatrix.sync.aligned.m8n8.x4.shared.b16 {%0,%1,%2,%3}, [%4];"
                 : "=r"(r[0]), "=r"(r[1]), "=r"(r[2]), "=r"(r[3]) : "r"(addr));
}
__device__ __forceinline__ void mma16816(float* d, const uint32_t* a, const uint32_t* b) {
    asm volatile(
        "mma.sync.aligned.m16n8k16.row.col.f32.f16.f16.f32 "
        "{%0,%1,%2,%3}, {%4,%5,%6,%7}, {%8,%9}, {%0,%1,%2,%3};"
        : "+f"(d[0]), "+f"(d[1]), "+f"(d[2]), "+f"(d[3])
        : "r"(a[0]), "r"(a[1]), "r"(a[2]), "r"(a[3]), "r"(b[0]), "r"(b[1]));
}
__device__ __forceinline__ void cpasync16(uint32_t dst, const void* src, int sz) {
    asm volatile("cp.async.cg.shared.global [%0], [%1], 16, %2;\n"
                 :: "r"(dst), "l"(src), "r"(sz) : "memory");
}
__device__ __forceinline__ void cpasync16(uint32_t dst, const void* src) {
    asm volatile("cp.async.cg.shared.global [%0], [%1], 16;\n"
                 :: "r"(dst), "l"(src) : "memory");
}
__device__ __forceinline__ void hsplit(float x, unsigned short& h, unsigned short& l) {
    __half hh = __float2half_rn(x);
    __half ll = __float2half_rn(x - __half2float(hh));
    h = __half_as_ushort(hh);
    l = __half_as_ushort(ll);
}

// ---------------- Stage 0 (fused prep) ----------------
__global__ void __launch_bounds__(256)
prep_kernel(const float* __restrict__ in,
            const float* __restrict__ mask,
            const float* __restrict__ wt)
{
    const int b = blockIdx.x;
    const int tid = threadIdx.x;
    if (b < 1024) {
        int n = b >> 8, bi = (b >> 4) & 15, bj = b & 15;
        int j = tid >> 4, i = tid & 15;
        int r = bi * 14 + j - 1;
        int c = bj * 14 + i - 1;
        float v = 0.0f;
        if (r >= 0 && r < 224 && c >= 0 && c < 224) v = mask[(n * 224 + r) * 224 + c];
        __shared__ double s[256];
        s[tid] = (double)v;
        __syncthreads();
        for (int off = 128; off > 0; off >>= 1) {
            if (tid < off) s[tid] += s[tid + off];
            __syncthreads();
        }
        if (tid == 0) g_active[b] = (s[0] > 128.0) ? 1 : 0;
    } else if (b < 1024 + 2304) {
        int bb = b - 1024;
        int pos = bb >> 8, f = bb & 255, c = tid;
        float x = wt[((size_t)((pos << 8) | c)) * 256 + f];
        unsigned short h, l;
        hsplit(x, h, l);
        size_t di = ((size_t)((pos << 8) | f)) * 256 + c;
        g_wt_h[di] = __ushort_as_half(h);
        g_wt_l[di] = __ushort_as_half(l);
    } else {
        size_t idx = (size_t)(b - 3328) * 256 + tid;
        const float4* in4 = reinterpret_cast<const float4*>(in);
        const size_t total4 = 12845056ull;
        const size_t stride = 6144ull * 256ull;
        for (size_t i = idx; i < total4; i += stride) {
            float4 v = in4[i];
            unsigned short h0, h1, h2, h3, l0, l1, l2, l3;
            hsplit(v.x, h0, l0); hsplit(v.y, h1, l1);
            hsplit(v.z, h2, l2); hsplit(v.w, h3, l3);
            uint2 hp, lp;
            hp.x = (uint32_t)h0 | ((uint32_t)h1 << 16);
            hp.y = (uint32_t)h2 | ((uint32_t)h3 << 16);
            lp.x = (uint32_t)l0 | ((uint32_t)l1 << 16);
            lp.y = (uint32_t)l2 | ((uint32_t)l3 << 16);
            *reinterpret_cast<uint2*>(g_in_h + 4 * i) = hp;
            *reinterpret_cast<uint2*>(g_in_l + 4 * i) = lp;
        }
    }
}

// ---------------- Stage 1: pipelined implicit-GEMM conv, N=128/CTA ----------------
// A per stage: 258 rows x 32B, hi+lo = 16512 B
// W per stage: 9 pos x 128 f rows x 32B, hi+lo = 73728 B
// XOR swizzle: byte(row, half) = row*32 + ((half ^ ((row>>2)&1)) << 4)
#define OFF_A   0u
#define A_STAGE 16512u
#define A_LO    8256u
#define OFF_W   33024u
#define W_STAGE 73728u
#define W_LO    36864u
#define SMEM_DYN 180480

__device__ __forceinline__ void issue_stage(uint32_t aBase, uint32_t wBase,
                                            int tid, int n, int r0, int c0,
                                            int fh, int cc)
{
    // A: 1024 ops (256 px x 2 halves x hi/lo)
    #pragma unroll
    for (int k = 0; k < 4; k++) {
        int i = tid + (k << 8);
        int arr  = i >> 9;
        int px   = (i & 511) >> 1;
        int half = i & 1;
        int r = r0 + (px >> 4), c = c0 + (px & 15);
        bool ok = ((unsigned)r < 224u) && ((unsigned)c < 224u);
        int rr = ok ? r : 0, cl = ok ? c : 0;
        const __half* gsrc = arr ? g_in_l : g_in_h;
        const void* src = gsrc + ((((size_t)(n * 224 + rr)) * 224 + cl) * 256
                                  + cc * 16 + half * 8);
        uint32_t dst = aBase + (uint32_t)arr * A_LO + (uint32_t)px * 32u
                     + (uint32_t)((half ^ ((px >> 2) & 1)) << 4);
        cpasync16(dst, src, ok ? 16 : 0);
    }
    // W: 4608 ops (1152 rows x 2 halves x hi/lo)
    #pragma unroll
    for (int k = 0; k < 18; k++) {
        int i = tid + (k << 8);
        int arr = (i >= 2304) ? 1 : 0;
        int j = i - arr * 2304;
        int row = j >> 1, half = j & 1;
        int pos = row >> 7, fl = row & 127;
        const __half* gsrc = arr ? g_wt_l : g_wt_h;
        const void* src = gsrc + (((size_t)(pos * 256 + fh * 128 + fl)) << 8)
                        + cc * 16 + half * 8;
        uint32_t dst = wBase + (uint32_t)arr * W_LO + (uint32_t)row * 32u
                     + (uint32_t)((half ^ ((row >> 2) & 1)) << 4);
        cpasync16(dst, src);
    }
}

__global__ void __launch_bounds__(256, 1)
conv_kernel(const float* __restrict__ bias, float* __restrict__ out)
{
    const int tile = blockIdx.x;
    const int fh   = blockIdx.y;         // 0..1 -> 128 F channels
    const int n = tile >> 8, bi = (tile >> 4) & 15, bj = tile & 15;
    const int tid = threadIdx.x;

    if (!g_active[tile]) {
        float4 z = make_float4(0.f, 0.f, 0.f, 0.f);
        for (int i = tid; i < 196 * 32; i += 256) {
            int px = i >> 5, q = i & 31;
            int oy = px / 14, ox = px - oy * 14;
            size_t o = (((size_t)(n * 224 + bi * 14 + oy)) * 224 + bj * 14 + ox) * 256
                       + fh * 128 + q * 4;
            *reinterpret_cast<float4*>(out + o) = z;
        }
        return;
    }

    extern __shared__ char sm[];
    const uint32_t sb = smem_to_u32(sm);

    const int l   = tid & 31;
    const int wid = tid >> 5;
    const int wm  = wid >> 2;            // 0..1 : M half (112 rows)
    const int wn  = wid & 3;             // 0..3 : 32-F slice within 128

    const int ra0   = wm * 112 + (l & 15);
    const int ahalf = l >> 4;
    const int rw0   = wn * 32 + ((l >> 4) & 1) * 8 + (l & 7);
    const uint32_t woff = (uint32_t)rw0 * 32u
        + (uint32_t)(((((l >> 3) & 1)) ^ ((rw0 >> 2) & 1)) << 4);
    const int rw1 = rw0 + 16;
    const uint32_t woff1 = (uint32_t)rw1 * 32u
        + (uint32_t)(((((l >> 3) & 1)) ^ ((rw1 >> 2) & 1)) << 4);

    const int r0 = bi * 14 - 1;
    const int c0 = bj * 14 - 1;

    // zero the pad rows (rows 256-257) in all 4 A regions
    if (tid < 64) {
        int s = (tid >> 5) & 1, arr = (tid >> 4) & 1;
        *reinterpret_cast<uint32_t*>(sm + OFF_A + s * A_STAGE + arr * A_LO
                                     + 8192 + (tid & 15) * 4) = 0;
    }

    const uint32_t aS[2] = { sb + OFF_A, sb + OFF_A + A_STAGE };
    const uint32_t wS[2] = { sb + OFF_W, sb + OFF_W + W_STAGE };

    float acc[7][16];
    #pragma unroll
    for (int t = 0; t < 7; t++)
        #pragma unroll
        for (int j = 0; j < 16; j++) acc[t][j] = 0.f;

    // prologue: stage 0
    issue_stage(aS[0], wS[0], tid, n, r0, c0, fh, 0);
    asm volatile("cp.async.commit_group;\n" ::: "memory");

    for (int cc = 0; cc < 16; cc++) {
        const int p = cc & 1;
        asm volatile("cp.async.wait_group 0;\n" ::: "memory");
        __syncthreads();
        if (cc < 15) {
            issue_stage(aS[p ^ 1], wS[p ^ 1], tid, n, r0, c0, fh, cc + 1);
            asm volatile("cp.async.commit_group;\n" ::: "memory");
        }

        const uint32_t aB = aS[p];
        const uint32_t wB = wS[p];
        #pragma unroll 1
        for (int pos = 0; pos < 9; pos++) {
            const int ky = pos / 3, kx = pos - ky * 3;
            const int ra = ra0 + ky * 16 + kx;
            const uint32_t aaddr = aB + (uint32_t)ra * 32u
                + (uint32_t)((ahalf ^ ((ra >> 2) & 1)) << 4);
            const uint32_t wbase = wB + (uint32_t)pos * 4096u;

            uint32_t wh[8], wl[8];
            ldsm4(wh,     wbase + woff);
            ldsm4(wh + 4, wbase + woff1);
            ldsm4(wl,     wbase + W_LO + woff);
            ldsm4(wl + 4, wbase + W_LO + woff1);

            uint32_t a[7][4];
            #pragma unroll
            for (int t = 0; t < 7; t++)
                ldsm4(a[t], aaddr + (uint32_t)t * 512u);
            #pragma unroll
            for (int t = 0; t < 7; t++) {
                #pragma unroll
                for (int g = 0; g < 4; g++)
                    mma16816(acc[t] + g * 4, a[t], wh + g * 2);
            }
            #pragma unroll
            for (int t = 0; t < 7; t++) {
                #pragma unroll
                for (int g = 0; g < 4; g++)
                    mma16816(acc[t] + g * 4, a[t], wl + g * 2);
            }
            #pragma unroll
            for (int t = 0; t < 7; t++)
                ldsm4(a[t], aaddr + A_LO + (uint32_t)t * 512u);
            #pragma unroll
            for (int t = 0; t < 7; t++) {
                #pragma unroll
                for (int g = 0; g < 4; g++)
                    mma16816(acc[t] + g * 4, a[t], wh + g * 2);
            }
        }
    }

    // ---- epilogue: bias + relu + store ----
    // n8 group g covers f0g = fh*128 + wn*32 + g*8 + (l&3)*2
    const int fbase = fh * 128 + wn * 32 + (l & 3) * 2;
    float bb[8];
    #pragma unroll
    for (int g = 0; g < 4; g++) {
        bb[g * 2 + 0] = bias[fbase + g * 8];
        bb[g * 2 + 1] = bias[fbase + g * 8 + 1];
    }

    #pragma unroll
    for (int t = 0; t < 7; t++) {
        int m_lo = wm * 112 + t * 16 + (l >> 2);
        #pragma unroll
        for (int h = 0; h < 2; h++) {
            int m = m_lo + h * 8;
            int oy = m >> 4, ox = m & 15;
            if (ox < 14) {
                float* p = out + (((size_t)(n * 224 + bi * 14 + oy)) * 224
                                  + bj * 14 + ox) * 256 + fbase;
                #pragma unroll
                for (int g = 0; g < 4; g++) {
                    float2 v;
                    v.x = fmaxf(acc[t][g * 4 + h * 2 + 0] + bb[g * 2 + 0], 0.f);
                    v.y = fmaxf(acc[t][g * 4 + h * 2 + 1] + bb[g * 2 + 1], 0.f);
                    *reinterpret_cast<float2*>(p + g * 8) = v;
                }
            }
        }
    }
}

extern "C" void kernel_launch(void* const* d_in, const int* in_sizes, int n_in,
                              void* d_out, int out_size) {
    const float* inputs = (const float*)d_in[0];
    const float* mask   = (const float*)d_in[1];
    const float* kernel = (const float*)d_in[2];
    const float* bias   = (const float*)d_in[3];
    float* out = (float*)d_out;

    cudaFuncSetAttribute(conv_kernel, cudaFuncAttributeMaxDynamicSharedMemorySize, SMEM_DYN);

    prep_kernel<<<9472, 256>>>(inputs, mask, kernel);
    dim3 grid(NTILES, 2);
    conv_kernel<<<grid, 256, SMEM_DYN>>>(bias, out);
}